// round 1
// baseline (speedup 1.0000x reference)
#include <cuda_runtime.h>

// ---------------------------------------------------------------------------
// ComplexAttention  (B=16, S=1024, D=1024)
//   6x linear (NT gemm + bias), scores = qr@kr (NN) + qi@ki^T (NT), softmax/8,
//   out = attn@vr, attn@vi (NN), complex LayerNorm -> [2,B,S,D]
// ---------------------------------------------------------------------------

#define BB 16
#define SS 1024
#define DD 1024
#define MTOT (BB * SS)                 // 16384
#define PLANE ((long long)MTOT * DD)   // 16,777,216 elements per real/imag plane

// Scratch (static device memory; allocation APIs are forbidden)
__device__ float g_qr[MTOT * DD];
__device__ float g_qi[MTOT * DD];
__device__ float g_kr[MTOT * DD];
__device__ float g_ki[MTOT * DD];
__device__ float g_vr[MTOT * DD];
__device__ float g_vi[MTOT * DD];
__device__ float g_sc[(long long)BB * SS * SS];
__device__ float g_or[MTOT * DD];
__device__ float g_oi[MTOT * DD];

// ---------------------------------------------------------------------------
// Tiled SGEMM: C[M,N] (+)= A[M,K] * op(B)  (+ bias)
//   TRANSB=1: B is [N,K] row-major (ld=K)   -> C = A * B^T
//   TRANSB=0: B is [K,N] row-major (ld=N)   -> C = A * B
//   A row-major ld=K, C row-major ld=N.
//   Tile 128x128x8, 256 threads, 8x8 per thread.
//   Requires M,N % 128 == 0, K % 8 == 0 (true for all uses here).
// ---------------------------------------------------------------------------
template <bool TRANSB, bool ACCUM, bool BIAS>
__global__ __launch_bounds__(256) void gemm128(
    const float* __restrict__ A, const float* __restrict__ B,
    float* __restrict__ C, const float* __restrict__ bias,
    int M, int N, int K,
    long long strA, long long strB, long long strC)
{
    __shared__ float As[8][128];
    __shared__ float Bs[8][128];

    const int b = blockIdx.z;
    A += (long long)b * strA;
    B += (long long)b * strB;
    C += (long long)b * strC;

    const int m0 = blockIdx.y * 128;
    const int n0 = blockIdx.x * 128;
    const int tid = threadIdx.x;
    const int tx = tid & 15;     // 0..15 -> n micro tile
    const int ty = tid >> 4;     // 0..15 -> m micro tile

    // global->shared load mapping (transpose loads)
    const int lrow = tid >> 1;          // 0..127
    const int lk4  = (tid & 1) * 4;     // 0 or 4

    float acc[8][8];
#pragma unroll
    for (int i = 0; i < 8; i++)
#pragma unroll
        for (int j = 0; j < 8; j++) acc[i][j] = 0.0f;

    for (int k0 = 0; k0 < K; k0 += 8) {
        // A tile -> As[k][m]
        float4 av = *(const float4*)&A[(long long)(m0 + lrow) * K + k0 + lk4];
        As[lk4 + 0][lrow] = av.x;
        As[lk4 + 1][lrow] = av.y;
        As[lk4 + 2][lrow] = av.z;
        As[lk4 + 3][lrow] = av.w;

        if (TRANSB) {
            float4 bv = *(const float4*)&B[(long long)(n0 + lrow) * K + k0 + lk4];
            Bs[lk4 + 0][lrow] = bv.x;
            Bs[lk4 + 1][lrow] = bv.y;
            Bs[lk4 + 2][lrow] = bv.z;
            Bs[lk4 + 3][lrow] = bv.w;
        } else {
            const int kk = tid >> 5;         // 0..7
            const int nn = (tid & 31) * 4;   // 0..124
            float4 bv = *(const float4*)&B[(long long)(k0 + kk) * N + n0 + nn];
            *(float4*)&Bs[kk][nn] = bv;
        }
        __syncthreads();

#pragma unroll
        for (int k = 0; k < 8; k++) {
            float a[8], bfr[8];
#pragma unroll
            for (int i = 0; i < 8; i++) a[i] = As[k][ty * 8 + i];
#pragma unroll
            for (int j = 0; j < 8; j++) bfr[j] = Bs[k][tx * 8 + j];
#pragma unroll
            for (int i = 0; i < 8; i++)
#pragma unroll
                for (int j = 0; j < 8; j++) acc[i][j] += a[i] * bfr[j];
        }
        __syncthreads();
    }

#pragma unroll
    for (int i = 0; i < 8; i++) {
        const int m = m0 + ty * 8 + i;
#pragma unroll
        for (int j = 0; j < 8; j += 4) {
            const int n = n0 + tx * 8 + j;
            float4 v = make_float4(acc[i][j], acc[i][j + 1], acc[i][j + 2], acc[i][j + 3]);
            if (BIAS) {
                const float4 bb = *(const float4*)&bias[n];
                v.x += bb.x; v.y += bb.y; v.z += bb.z; v.w += bb.w;
            }
            if (ACCUM) {
                const float4 o = *(const float4*)&C[(long long)m * N + n];
                v.x += o.x; v.y += o.y; v.z += o.z; v.w += o.w;
            }
            *(float4*)&C[(long long)m * N + n] = v;
        }
    }
}

// ---------------------------------------------------------------------------
// Softmax over rows of length 1024, with pre-scale 1/sqrt(64) = 0.125
// one block (256 threads) per row, 4 elems/thread
// ---------------------------------------------------------------------------
__global__ __launch_bounds__(256) void softmax_kernel(float* __restrict__ sc)
{
    __shared__ float sbuf[8];
    const long long row = blockIdx.x;
    float* x = sc + row * (long long)SS;
    const int t = threadIdx.x;
    const int lane = t & 31, warp = t >> 5;

    float4 v = *(float4*)&x[t * 4];
    const float s = 0.125f;
    v.x *= s; v.y *= s; v.z *= s; v.w *= s;

    float m = fmaxf(fmaxf(v.x, v.y), fmaxf(v.z, v.w));
#pragma unroll
    for (int o = 16; o > 0; o >>= 1) m = fmaxf(m, __shfl_xor_sync(0xffffffffu, m, o));
    if (lane == 0) sbuf[warp] = m;
    __syncthreads();
    if (t == 0) {
        float mm = sbuf[0];
#pragma unroll
        for (int i = 1; i < 8; i++) mm = fmaxf(mm, sbuf[i]);
        sbuf[0] = mm;
    }
    __syncthreads();
    m = sbuf[0];
    __syncthreads();

    v.x = __expf(v.x - m);
    v.y = __expf(v.y - m);
    v.z = __expf(v.z - m);
    v.w = __expf(v.w - m);

    float sum = v.x + v.y + v.z + v.w;
#pragma unroll
    for (int o = 16; o > 0; o >>= 1) sum += __shfl_xor_sync(0xffffffffu, sum, o);
    if (lane == 0) sbuf[warp] = sum;
    __syncthreads();
    if (t == 0) {
        float ss2 = 0.0f;
#pragma unroll
        for (int i = 0; i < 8; i++) ss2 += sbuf[i];
        sbuf[0] = ss2;
    }
    __syncthreads();
    const float inv = 1.0f / sbuf[0];

    v.x *= inv; v.y *= inv; v.z *= inv; v.w *= inv;
    *(float4*)&x[t * 4] = v;
}

// ---------------------------------------------------------------------------
// Complex LayerNorm over D=1024 per (b,s) row.
//   z = zr + i*zi ; mean/var in complex arithmetic; std = complex sqrt(var+eps)
//   y = a2 * (z-mean)/std + b2  (a2,b2 real) ; out[0]=Re, out[1]=Im
// ---------------------------------------------------------------------------
__global__ __launch_bounds__(256) void ln_kernel(
    const float* __restrict__ Zr, const float* __restrict__ Zi,
    const float* __restrict__ a2, const float* __restrict__ b2,
    float* __restrict__ out)
{
    __shared__ float2 sbuf[8];
    const long long row = blockIdx.x;
    const int t = threadIdx.x;
    const int lane = t & 31, warp = t >> 5;

    const float4 r  = *(const float4*)&Zr[row * DD + t * 4];
    const float4 im = *(const float4*)&Zi[row * DD + t * 4];

    // mean (complex)
    float2 s = make_float2(r.x + r.y + r.z + r.w, im.x + im.y + im.z + im.w);
#pragma unroll
    for (int o = 16; o > 0; o >>= 1) {
        s.x += __shfl_xor_sync(0xffffffffu, s.x, o);
        s.y += __shfl_xor_sync(0xffffffffu, s.y, o);
    }
    if (lane == 0) sbuf[warp] = s;
    __syncthreads();
    if (t == 0) {
        float2 a = sbuf[0];
#pragma unroll
        for (int i = 1; i < 8; i++) { a.x += sbuf[i].x; a.y += sbuf[i].y; }
        sbuf[0] = a;
    }
    __syncthreads();
    const float mr = sbuf[0].x * (1.0f / 1024.0f);
    const float mi = sbuf[0].y * (1.0f / 1024.0f);
    __syncthreads();

    float dr[4] = { r.x - mr,  r.y - mr,  r.z - mr,  r.w - mr };
    float di[4] = { im.x - mi, im.y - mi, im.z - mi, im.w - mi };

    // var (complex square, not |.|^2)
    float2 vv = make_float2(0.0f, 0.0f);
#pragma unroll
    for (int j = 0; j < 4; j++) {
        vv.x += dr[j] * dr[j] - di[j] * di[j];
        vv.y += 2.0f * dr[j] * di[j];
    }
#pragma unroll
    for (int o = 16; o > 0; o >>= 1) {
        vv.x += __shfl_xor_sync(0xffffffffu, vv.x, o);
        vv.y += __shfl_xor_sync(0xffffffffu, vv.y, o);
    }
    if (lane == 0) sbuf[warp] = vv;
    __syncthreads();
    if (t == 0) {
        float2 a = sbuf[0];
#pragma unroll
        for (int i = 1; i < 8; i++) { a.x += sbuf[i].x; a.y += sbuf[i].y; }
        sbuf[0] = a;
    }
    __syncthreads();
    const float var_r = sbuf[0].x * (1.0f / 1024.0f) + 1e-6f;
    const float var_i = sbuf[0].y * (1.0f / 1024.0f);

    // principal complex sqrt of (var_r + i var_i)
    const float mag = sqrtf(var_r * var_r + var_i * var_i);
    const float sr  = sqrtf(fmaxf(0.5f * (mag + var_r), 0.0f));
    const float su  = sqrtf(fmaxf(0.5f * (mag - var_r), 0.0f));
    const float si  = (var_i >= 0.0f) ? su : -su;
    // 1/std = conj(std)/|std|^2 ; |std|^2 = |var+eps| = mag
    const float invmag = 1.0f / mag;
    const float cr =  sr * invmag;
    const float ci = -si * invmag;

    const int d0 = t * 4;
    const float4 av = *(const float4*)&a2[d0];
    const float4 bv = *(const float4*)&b2[d0];
    const float aa[4] = { av.x, av.y, av.z, av.w };
    const float bb[4] = { bv.x, bv.y, bv.z, bv.w };

    float4 yr, yi;
    float* yrp = &yr.x;
    float* yip = &yi.x;
#pragma unroll
    for (int j = 0; j < 4; j++) {
        const float ur = dr[j] * cr - di[j] * ci;
        const float ui = dr[j] * ci + di[j] * cr;
        yrp[j] = aa[j] * ur + bb[j];
        yip[j] = aa[j] * ui;
    }
    *(float4*)&out[row * DD + d0]         = yr;
    *(float4*)&out[PLANE + row * DD + d0] = yi;
}

// ---------------------------------------------------------------------------
// launch
// ---------------------------------------------------------------------------
extern "C" void kernel_launch(void* const* d_in, const int* in_sizes, int n_in,
                              void* d_out, int out_size)
{
    const float* q_real = (const float*)d_in[0];
    const float* q_imag = (const float*)d_in[1];
    const float* k_real = (const float*)d_in[2];
    const float* k_imag = (const float*)d_in[3];
    const float* v_real = (const float*)d_in[4];
    const float* v_imag = (const float*)d_in[5];
    const float* Wq_r = (const float*)d_in[6];
    const float* bq_r = (const float*)d_in[7];
    const float* Wq_i = (const float*)d_in[8];
    const float* bq_i = (const float*)d_in[9];
    const float* Wk_r = (const float*)d_in[10];
    const float* bk_r = (const float*)d_in[11];
    const float* Wk_i = (const float*)d_in[12];
    const float* bk_i = (const float*)d_in[13];
    const float* Wv_r = (const float*)d_in[14];
    const float* bv_r = (const float*)d_in[15];
    const float* Wv_i = (const float*)d_in[16];
    const float* bv_i = (const float*)d_in[17];
    const float* a_2  = (const float*)d_in[18];
    const float* b_2  = (const float*)d_in[19];

    float *qr, *qi, *kr, *ki, *vr, *vi, *sc, *zr, *zi;
    cudaGetSymbolAddress((void**)&qr, g_qr);
    cudaGetSymbolAddress((void**)&qi, g_qi);
    cudaGetSymbolAddress((void**)&kr, g_kr);
    cudaGetSymbolAddress((void**)&ki, g_ki);
    cudaGetSymbolAddress((void**)&vr, g_vr);
    cudaGetSymbolAddress((void**)&vi, g_vi);
    cudaGetSymbolAddress((void**)&sc, g_sc);
    cudaGetSymbolAddress((void**)&zr, g_or);
    cudaGetSymbolAddress((void**)&zi, g_oi);

    const dim3 blk(256);
    const dim3 gLin(DD / 128, MTOT / 128, 1);     // (8, 128)
    const long long st = (long long)SS * SS;      // 1048576 (== S*D)

    // 6 linear projections: X @ W^T + b
    gemm128<true, false, true><<<gLin, blk>>>(q_real, Wq_r, qr, bq_r, MTOT, DD, DD, 0, 0, 0);
    gemm128<true, false, true><<<gLin, blk>>>(q_imag, Wq_i, qi, bq_i, MTOT, DD, DD, 0, 0, 0);
    gemm128<true, false, true><<<gLin, blk>>>(k_real, Wk_r, kr, bk_r, MTOT, DD, DD, 0, 0, 0);
    gemm128<true, false, true><<<gLin, blk>>>(k_imag, Wk_i, ki, bk_i, MTOT, DD, DD, 0, 0, 0);
    gemm128<true, false, true><<<gLin, blk>>>(v_real, Wv_r, vr, bv_r, MTOT, DD, DD, 0, 0, 0);
    gemm128<true, false, true><<<gLin, blk>>>(v_imag, Wv_i, vi, bv_i, MTOT, DD, DD, 0, 0, 0);

    // scores = qr @ kr  (NN, faithful to the source's no-op transpose)
    //        + qi @ ki^T (NT, accumulate)
    const dim3 gS(SS / 128, SS / 128, BB);        // (8, 8, 16)
    gemm128<false, false, false><<<gS, blk>>>(qr, kr, sc, nullptr, SS, SS, DD, st, st, st);
    gemm128<true,  true,  false><<<gS, blk>>>(qi, ki, sc, nullptr, SS, SS, DD, st, st, st);

    // softmax(scores / 8) in place
    softmax_kernel<<<MTOT, 256>>>(sc);

    // out = attn @ v (real and imag)
    gemm128<false, false, false><<<gS, blk>>>(sc, vr, zr, nullptr, SS, DD, SS, st, st, st);
    gemm128<false, false, false><<<gS, blk>>>(sc, vi, zi, nullptr, SS, DD, SS, st, st, st);

    // complex LayerNorm -> [2, B, S, D]
    ln_kernel<<<MTOT, 256>>>(zr, zi, a_2, b_2, (float*)d_out);
}

// round 4
// speedup vs baseline: 2.2259x; 2.2259x over previous
#include <cuda_runtime.h>
#include <cuda_bf16.h>
#include <cstdint>

// ===========================================================================
// ComplexAttention (B=16, S=1024, D=1024)
// bf16 3-term-split GEMMs on mma.sync.m16n8k16 (compute_103-safe; no tcgen05)
// ===========================================================================

#define BB 16
#define SS 1024
#define DD 1024
#define MTOT (BB * SS)                  // 16384
#define PLANE ((long long)MTOT * DD)

// ---------------- scratch (static device memory) ---------------------------
__device__ float g_qr[MTOT * DD];
__device__ float g_qi[MTOT * DD];
__device__ float g_kr[MTOT * DD];
__device__ float g_ki[MTOT * DD];
__device__ float g_vr[MTOT * DD];
__device__ float g_vi[MTOT * DD];
__device__ float g_sc[(long long)MTOT * DD];
__device__ float g_or[MTOT * DD];
__device__ float g_oi[MTOT * DD];

__device__ __nv_bfloat16 g_inh[MTOT * DD];     // input split (reused)
__device__ __nv_bfloat16 g_inl[MTOT * DD];
__device__ __nv_bfloat16 g_wh[DD * DD];        // weight split (reused)
__device__ __nv_bfloat16 g_wl[DD * DD];
__device__ __nv_bfloat16 g_qrh[MTOT * DD];     // qr split; later attn split
__device__ __nv_bfloat16 g_qrl[MTOT * DD];
__device__ __nv_bfloat16 g_qih[MTOT * DD];     // qi split; later vr^T split
__device__ __nv_bfloat16 g_qil[MTOT * DD];
__device__ __nv_bfloat16 g_kih[MTOT * DD];     // ki split; later vi^T split
__device__ __nv_bfloat16 g_kil[MTOT * DD];
__device__ __nv_bfloat16 g_kth[MTOT * DD];     // kr^T split
__device__ __nv_bfloat16 g_ktl[MTOT * DD];

// ---------------- asm helpers ----------------------------------------------
__device__ __forceinline__ uint32_t smem_u32(const void* p) {
    uint32_t a;
    asm("{ .reg .u64 t; cvta.to.shared.u64 t, %1; cvt.u32.u64 %0, t; }" : "=r"(a) : "l"(p));
    return a;
}
#define CPA16(dst, src) \
    asm volatile("cp.async.cg.shared.global [%0], [%1], 16;" :: "r"(dst), "l"(src) : "memory")
#define CPA_COMMIT() asm volatile("cp.async.commit_group;" ::: "memory")
#define CPA_WAIT3()  asm volatile("cp.async.wait_group 3;" ::: "memory")

#define MMA_BF16(d, a, b) \
    asm volatile("mma.sync.aligned.m16n8k16.row.col.f32.bf16.bf16.f32 " \
                 "{%0,%1,%2,%3}, {%4,%5,%6,%7}, {%8,%9}, {%0,%1,%2,%3};" \
                 : "+f"((d)[0]), "+f"((d)[1]), "+f"((d)[2]), "+f"((d)[3]) \
                 : "r"((a)[0]), "r"((a)[1]), "r"((a)[2]), "r"((a)[3]), \
                   "r"((b)[0]), "r"((b)[1]))

// ---------------- mma GEMM --------------------------------------------------
// C[m,n] = sum_k A[m,k] * B[n,k]; A,B given as bf16 hi/lo split, K-stride 1024.
// niter = K/32; for niter=64 two phases: iters >=32 use A1/B1 (k rebased).
// Tile 128x128x32, 8 warps (2x4), warp tile 64x32, 4-stage cp.async pipeline.
#define STAGES 4
#define PADB 80                          // padded row bytes (32 halves + 8 pad)
#define T_AH 0
#define T_AL 10240
#define T_BH 20480
#define T_BL 30720
#define STAGE_B 40960
#define SMEM_B (STAGES * STAGE_B)        // 163840

__global__ __launch_bounds__(256, 1) void mmagemm(
    const __nv_bfloat16* __restrict__ A0h, const __nv_bfloat16* __restrict__ A0l,
    const __nv_bfloat16* __restrict__ B0h, const __nv_bfloat16* __restrict__ B0l,
    const __nv_bfloat16* __restrict__ A1h, const __nv_bfloat16* __restrict__ A1l,
    const __nv_bfloat16* __restrict__ B1h, const __nv_bfloat16* __restrict__ B1l,
    const float* __restrict__ bias, float* __restrict__ C,
    int niter, int batched)
{
    extern __shared__ char smem[];
    const uint32_t usm = smem_u32(smem);
    const int tid = threadIdx.x;
    const int lane = tid & 31, wid = tid >> 5;
    const int wm = wid & 1, wn = wid >> 1;

    const int m0 = blockIdx.y * 128, n0 = blockIdx.x * 128;
    const long long zo = batched ? (long long)blockIdx.z * SS * DD : 0;

    // per-thread copy mapping: row = tid>>1, 32-byte half-chunk = tid&1
    const int crow = tid >> 1;
    const int cofs = (tid & 1) * 32;                    // byte offset in 64B row
    const long long gaBase = zo + (long long)(m0 + crow) * DD + (tid & 1) * 16;
    const long long gbBase = zo + (long long)(n0 + crow) * DD + (tid & 1) * 16;

    auto issue = [&](int i) {
        const bool p1 = (i >= 32);
        const __nv_bfloat16* Ah = p1 ? A1h : A0h;
        const __nv_bfloat16* Al = p1 ? A1l : A0l;
        const __nv_bfloat16* Bh = p1 ? B1h : B0h;
        const __nv_bfloat16* Bl = p1 ? B1l : B0l;
        const int kk = (p1 ? i - 32 : i) * 32;          // half offset in K
        const uint32_t sb = usm + (uint32_t)(i & 3) * STAGE_B + crow * PADB + cofs;
        const long long ga = gaBase + kk;
        const long long gb = gbBase + kk;
        CPA16(sb + T_AH,      Ah + ga); CPA16(sb + T_AH + 16, Ah + ga + 8);
        CPA16(sb + T_AL,      Al + ga); CPA16(sb + T_AL + 16, Al + ga + 8);
        CPA16(sb + T_BH,      Bh + gb); CPA16(sb + T_BH + 16, Bh + gb + 8);
        CPA16(sb + T_BL,      Bl + gb); CPA16(sb + T_BL + 16, Bl + gb + 8);
    };

    float acc[4][4][4];
#pragma unroll
    for (int mi = 0; mi < 4; mi++)
#pragma unroll
        for (int ni = 0; ni < 4; ni++)
#pragma unroll
            for (int j = 0; j < 4; j++) acc[mi][ni][j] = 0.0f;

    // prologue: 3 stages in flight
    issue(0); CPA_COMMIT();
    issue(1); CPA_COMMIT();
    issue(2); CPA_COMMIT();

    for (int i = 0; i < niter; i++) {
        if (i + 3 < niter) issue(i + 3);
        CPA_COMMIT();
        CPA_WAIT3();
        __syncthreads();

        const char* sb = smem + (size_t)(i & 3) * STAGE_B;
        const char* Ah = sb + T_AH;
        const char* Al = sb + T_AL;
        const char* Bh = sb + T_BH;
        const char* Bl = sb + T_BL;

#pragma unroll
        for (int ks = 0; ks < 2; ks++) {
            const int kb2 = (ks * 16 + (lane & 3) * 2) * 2;   // byte offset of k
            uint32_t ah[4][4], al[4][4], bh[4][2], bl[4][2];
#pragma unroll
            for (int mi = 0; mi < 4; mi++) {
                const int r = wm * 64 + mi * 16 + (lane >> 2);
                ah[mi][0] = *(const uint32_t*)(Ah + r * PADB + kb2);
                ah[mi][1] = *(const uint32_t*)(Ah + (r + 8) * PADB + kb2);
                ah[mi][2] = *(const uint32_t*)(Ah + r * PADB + kb2 + 16);
                ah[mi][3] = *(const uint32_t*)(Ah + (r + 8) * PADB + kb2 + 16);
                al[mi][0] = *(const uint32_t*)(Al + r * PADB + kb2);
                al[mi][1] = *(const uint32_t*)(Al + (r + 8) * PADB + kb2);
                al[mi][2] = *(const uint32_t*)(Al + r * PADB + kb2 + 16);
                al[mi][3] = *(const uint32_t*)(Al + (r + 8) * PADB + kb2 + 16);
            }
#pragma unroll
            for (int ni = 0; ni < 4; ni++) {
                const int n = wn * 32 + ni * 8 + (lane >> 2);
                bh[ni][0] = *(const uint32_t*)(Bh + n * PADB + kb2);
                bh[ni][1] = *(const uint32_t*)(Bh + n * PADB + kb2 + 16);
                bl[ni][0] = *(const uint32_t*)(Bl + n * PADB + kb2);
                bl[ni][1] = *(const uint32_t*)(Bl + n * PADB + kb2 + 16);
            }
#pragma unroll
            for (int mi = 0; mi < 4; mi++)
#pragma unroll
                for (int ni = 0; ni < 4; ni++) {
                    MMA_BF16(acc[mi][ni], ah[mi], bh[ni]);
                    MMA_BF16(acc[mi][ni], ah[mi], bl[ni]);
                    MMA_BF16(acc[mi][ni], al[mi], bh[ni]);
                }
        }
        __syncthreads();
    }

    // epilogue
    const long long crow0 = (batched ? (long long)blockIdx.z * SS : 0) + m0;
#pragma unroll
    for (int mi = 0; mi < 4; mi++) {
        const long long r = crow0 + wm * 64 + mi * 16 + (lane >> 2);
#pragma unroll
        for (int ni = 0; ni < 4; ni++) {
            const int c = n0 + wn * 32 + ni * 8 + (lane & 3) * 2;
            float bx = 0.0f, by = 0.0f;
            if (bias) { bx = bias[c]; by = bias[c + 1]; }
            float2 v0 = make_float2(acc[mi][ni][0] + bx, acc[mi][ni][1] + by);
            float2 v1 = make_float2(acc[mi][ni][2] + bx, acc[mi][ni][3] + by);
            *(float2*)&C[r * DD + c]       = v0;
            *(float2*)&C[(r + 8) * DD + c] = v1;
        }
    }
}

// ---------------- split / transpose-split -----------------------------------
__global__ __launch_bounds__(256) void split_kernel(
    const float* __restrict__ x, __nv_bfloat16* __restrict__ h,
    __nv_bfloat16* __restrict__ l, long long n4)
{
    const long long i = (long long)blockIdx.x * 256 + threadIdx.x;
    if (i >= n4) return;
    const float4 v = ((const float4*)x)[i];
    union { __nv_bfloat16 b[4]; uint2 u; } H, L;
    H.b[0] = __float2bfloat16(v.x); H.b[1] = __float2bfloat16(v.y);
    H.b[2] = __float2bfloat16(v.z); H.b[3] = __float2bfloat16(v.w);
    L.b[0] = __float2bfloat16(v.x - __bfloat162float(H.b[0]));
    L.b[1] = __float2bfloat16(v.y - __bfloat162float(H.b[1]));
    L.b[2] = __float2bfloat16(v.z - __bfloat162float(H.b[2]));
    L.b[3] = __float2bfloat16(v.w - __bfloat162float(H.b[3]));
    ((uint2*)h)[i] = H.u;
    ((uint2*)l)[i] = L.u;
}

__global__ __launch_bounds__(256) void tsplit_kernel(
    const float* __restrict__ in, __nv_bfloat16* __restrict__ h,
    __nv_bfloat16* __restrict__ l)
{
    __shared__ float t[32][33];
    const int b = blockIdx.z;
    const long long base = (long long)b * SS * DD;
    const int j0 = blockIdx.x * 32, i0 = blockIdx.y * 32;
    const int tx = threadIdx.x, ty = threadIdx.y;
#pragma unroll
    for (int r = 0; r < 4; r++)
        t[ty + 8 * r][tx] = in[base + (long long)(i0 + ty + 8 * r) * DD + j0 + tx];
    __syncthreads();
#pragma unroll
    for (int r = 0; r < 4; r++) {
        const float v = t[tx][ty + 8 * r];
        const __nv_bfloat16 hh = __float2bfloat16(v);
        const __nv_bfloat16 ll = __float2bfloat16(v - __bfloat162float(hh));
        const long long o = base + (long long)(j0 + ty + 8 * r) * DD + i0 + tx;
        h[o] = hh; l[o] = ll;
    }
}

// ---------------- softmax (rows of 1024, pre-scale 0.125) -------------------
__global__ __launch_bounds__(256) void softmax_kernel(float* __restrict__ sc)
{
    __shared__ float sbuf[8];
    const long long row = blockIdx.x;
    float* x = sc + row * (long long)SS;
    const int t = threadIdx.x;
    const int lane = t & 31, warp = t >> 5;

    float4 v = *(float4*)&x[t * 4];
    const float s = 0.125f;
    v.x *= s; v.y *= s; v.z *= s; v.w *= s;

    float m = fmaxf(fmaxf(v.x, v.y), fmaxf(v.z, v.w));
#pragma unroll
    for (int o = 16; o > 0; o >>= 1) m = fmaxf(m, __shfl_xor_sync(0xffffffffu, m, o));
    if (lane == 0) sbuf[warp] = m;
    __syncthreads();
    if (t == 0) {
        float mm = sbuf[0];
#pragma unroll
        for (int i = 1; i < 8; i++) mm = fmaxf(mm, sbuf[i]);
        sbuf[0] = mm;
    }
    __syncthreads();
    m = sbuf[0];
    __syncthreads();

    v.x = __expf(v.x - m); v.y = __expf(v.y - m);
    v.z = __expf(v.z - m); v.w = __expf(v.w - m);

    float sum = v.x + v.y + v.z + v.w;
#pragma unroll
    for (int o = 16; o > 0; o >>= 1) sum += __shfl_xor_sync(0xffffffffu, sum, o);
    if (lane == 0) sbuf[warp] = sum;
    __syncthreads();
    if (t == 0) {
        float ss2 = 0.0f;
#pragma unroll
        for (int i = 0; i < 8; i++) ss2 += sbuf[i];
        sbuf[0] = ss2;
    }
    __syncthreads();
    const float inv = 1.0f / sbuf[0];
    v.x *= inv; v.y *= inv; v.z *= inv; v.w *= inv;
    *(float4*)&x[t * 4] = v;
}

// ---------------- complex LayerNorm -----------------------------------------
__global__ __launch_bounds__(256) void ln_kernel(
    const float* __restrict__ Zr, const float* __restrict__ Zi,
    const float* __restrict__ a2, const float* __restrict__ b2,
    float* __restrict__ out)
{
    __shared__ float2 sbuf[8];
    const long long row = blockIdx.x;
    const int t = threadIdx.x;
    const int lane = t & 31, warp = t >> 5;

    const float4 r  = *(const float4*)&Zr[row * DD + t * 4];
    const float4 im = *(const float4*)&Zi[row * DD + t * 4];

    float2 s = make_float2(r.x + r.y + r.z + r.w, im.x + im.y + im.z + im.w);
#pragma unroll
    for (int o = 16; o > 0; o >>= 1) {
        s.x += __shfl_xor_sync(0xffffffffu, s.x, o);
        s.y += __shfl_xor_sync(0xffffffffu, s.y, o);
    }
    if (lane == 0) sbuf[warp] = s;
    __syncthreads();
    if (t == 0) {
        float2 a = sbuf[0];
#pragma unroll
        for (int i = 1; i < 8; i++) { a.x += sbuf[i].x; a.y += sbuf[i].y; }
        sbuf[0] = a;
    }
    __syncthreads();
    const float mr = sbuf[0].x * (1.0f / 1024.0f);
    const float mi = sbuf[0].y * (1.0f / 1024.0f);
    __syncthreads();

    float dr[4] = { r.x - mr,  r.y - mr,  r.z - mr,  r.w - mr };
    float di[4] = { im.x - mi, im.y - mi, im.z - mi, im.w - mi };

    float2 vv = make_float2(0.0f, 0.0f);
#pragma unroll
    for (int j = 0; j < 4; j++) {
        vv.x += dr[j] * dr[j] - di[j] * di[j];
        vv.y += 2.0f * dr[j] * di[j];
    }
#pragma unroll
    for (int o = 16; o > 0; o >>= 1) {
        vv.x += __shfl_xor_sync(0xffffffffu, vv.x, o);
        vv.y += __shfl_xor_sync(0xffffffffu, vv.y, o);
    }
    if (lane == 0) sbuf[warp] = vv;
    __syncthreads();
    if (t == 0) {
        float2 a = sbuf[0];
#pragma unroll
        for (int i = 1; i < 8; i++) { a.x += sbuf[i].x; a.y += sbuf[i].y; }
        sbuf[0] = a;
    }
    __syncthreads();
    const float var_r = sbuf[0].x * (1.0f / 1024.0f) + 1e-6f;
    const float var_i = sbuf[0].y * (1.0f / 1024.0f);

    const float mag = sqrtf(var_r * var_r + var_i * var_i);
    const float sr  = sqrtf(fmaxf(0.5f * (mag + var_r), 0.0f));
    const float su  = sqrtf(fmaxf(0.5f * (mag - var_r), 0.0f));
    const float si  = (var_i >= 0.0f) ? su : -su;
    const float invmag = 1.0f / mag;
    const float cr =  sr * invmag;
    const float ci = -si * invmag;

    const int d0 = t * 4;
    const float4 av = *(const float4*)&a2[d0];
    const float4 bv = *(const float4*)&b2[d0];
    const float aa[4] = { av.x, av.y, av.z, av.w };
    const float bb[4] = { bv.x, bv.y, bv.z, bv.w };

    float4 yr, yi;
    float* yrp = &yr.x;
    float* yip = &yi.x;
#pragma unroll
    for (int j = 0; j < 4; j++) {
        const float ur = dr[j] * cr - di[j] * ci;
        const float ui = dr[j] * ci + di[j] * cr;
        yrp[j] = aa[j] * ur + bb[j];
        yip[j] = aa[j] * ui;
    }
    *(float4*)&out[row * DD + d0]         = yr;
    *(float4*)&out[PLANE + row * DD + d0] = yi;
}

// ---------------- host ------------------------------------------------------
extern "C" void kernel_launch(void* const* d_in, const int* in_sizes, int n_in,
                              void* d_out, int out_size)
{
    const float* q_real = (const float*)d_in[0];
    const float* q_imag = (const float*)d_in[1];
    const float* k_real = (const float*)d_in[2];
    const float* k_imag = (const float*)d_in[3];
    const float* v_real = (const float*)d_in[4];
    const float* v_imag = (const float*)d_in[5];
    const float* Wq_r = (const float*)d_in[6];   const float* bq_r = (const float*)d_in[7];
    const float* Wq_i = (const float*)d_in[8];   const float* bq_i = (const float*)d_in[9];
    const float* Wk_r = (const float*)d_in[10];  const float* bk_r = (const float*)d_in[11];
    const float* Wk_i = (const float*)d_in[12];  const float* bk_i = (const float*)d_in[13];
    const float* Wv_r = (const float*)d_in[14];  const float* bv_r = (const float*)d_in[15];
    const float* Wv_i = (const float*)d_in[16];  const float* bv_i = (const float*)d_in[17];
    const float* a_2  = (const float*)d_in[18];
    const float* b_2  = (const float*)d_in[19];

    float *qr, *qi, *kr, *ki, *vr, *vi, *sc, *zr, *zi;
    cudaGetSymbolAddress((void**)&qr, g_qr);  cudaGetSymbolAddress((void**)&qi, g_qi);
    cudaGetSymbolAddress((void**)&kr, g_kr);  cudaGetSymbolAddress((void**)&ki, g_ki);
    cudaGetSymbolAddress((void**)&vr, g_vr);  cudaGetSymbolAddress((void**)&vi, g_vi);
    cudaGetSymbolAddress((void**)&sc, g_sc);
    cudaGetSymbolAddress((void**)&zr, g_or);  cudaGetSymbolAddress((void**)&zi, g_oi);

    __nv_bfloat16 *inh, *inl, *wh, *wl, *qrh, *qrl, *qih, *qil, *kih, *kil, *kth, *ktl;
    cudaGetSymbolAddress((void**)&inh, g_inh); cudaGetSymbolAddress((void**)&inl, g_inl);
    cudaGetSymbolAddress((void**)&wh,  g_wh);  cudaGetSymbolAddress((void**)&wl,  g_wl);
    cudaGetSymbolAddress((void**)&qrh, g_qrh); cudaGetSymbolAddress((void**)&qrl, g_qrl);
    cudaGetSymbolAddress((void**)&qih, g_qih); cudaGetSymbolAddress((void**)&qil, g_qil);
    cudaGetSymbolAddress((void**)&kih, g_kih); cudaGetSymbolAddress((void**)&kil, g_kil);
    cudaGetSymbolAddress((void**)&kth, g_kth); cudaGetSymbolAddress((void**)&ktl, g_ktl);

    cudaFuncSetAttribute(mmagemm, cudaFuncAttributeMaxDynamicSharedMemorySize, SMEM_B);

    const long long nBig = (long long)MTOT * DD / 4;   // float4 count
    const long long nW   = (long long)DD * DD / 4;
    const int gBig = (int)(nBig / 256), gW = (int)(nW / 256);
    const dim3 gLin(DD / 128, MTOT / 128, 1);          // (8, 128)
    const dim3 gBat(DD / 128, SS / 128, BB);           // (8, 8, 16)
    const dim3 gT(32, 32, 16);
    const dim3 bT(32, 8);

    // ---- 6 linear projections: C = X @ W^T + b ----
    const float* X[6]  = { q_real, q_imag, k_real, k_imag, v_real, v_imag };
    const float* W[6]  = { Wq_r, Wq_i, Wk_r, Wk_i, Wv_r, Wv_i };
    const float* Bv[6] = { bq_r, bq_i, bk_r, bk_i, bv_r, bv_i };
    float* O[6]        = { qr, qi, kr, ki, vr, vi };
    for (int j = 0; j < 6; j++) {
        split_kernel<<<gBig, 256>>>(X[j], inh, inl, nBig);
        split_kernel<<<gW,   256>>>(W[j], wh, wl, nW);
        mmagemm<<<gLin, 256, SMEM_B>>>(inh, inl, wh, wl,
                                       inh, inl, wh, wl,
                                       Bv[j], O[j], 32, 0);
    }

    // ---- scores = qr @ kr (NN via kr^T) + qi @ ki^T  (K = 2048, two-phase) ----
    split_kernel<<<gBig, 256>>>(qr, qrh, qrl, nBig);
    split_kernel<<<gBig, 256>>>(qi, qih, qil, nBig);
    split_kernel<<<gBig, 256>>>(ki, kih, kil, nBig);
    tsplit_kernel<<<gT, bT>>>(kr, kth, ktl);
    mmagemm<<<gBat, 256, SMEM_B>>>(qrh, qrl, kth, ktl,
                                   qih, qil, kih, kil,
                                   nullptr, sc, 64, 1);

    softmax_kernel<<<MTOT, 256>>>(sc);

    // ---- out = attn @ v (real & imag), NN via v^T; reuse split buffers ----
    split_kernel<<<gBig, 256>>>(sc, qrh, qrl, nBig);   // attn -> qrh/qrl
    tsplit_kernel<<<gT, bT>>>(vr, qih, qil);           // vr^T -> qih/qil
    tsplit_kernel<<<gT, bT>>>(vi, kih, kil);           // vi^T -> kih/kil
    mmagemm<<<gBat, 256, SMEM_B>>>(qrh, qrl, qih, qil,
                                   qrh, qrl, qih, qil,
                                   nullptr, zr, 32, 1);
    mmagemm<<<gBat, 256, SMEM_B>>>(qrh, qrl, kih, kil,
                                   qrh, qrl, kih, kil,
                                   nullptr, zi, 32, 1);

    // ---- complex LayerNorm -> [2, B, S, D] ----
    ln_kernel<<<MTOT, 256>>>(zr, zi, a_2, b_2, (float*)d_out);
}